// round 8
// baseline (speedup 1.0000x reference)
#include <cuda_runtime.h>
#include <cuda_fp16.h>
#include <cstdint>

#define BSZ   64
#define FD    256
#define MD    128
#define NBINS 8
#define NPAIR (BSZ * (BSZ + 1) / 2)     // 2080
#define KCH   64                        // K elements per SMEM chunk
#define NCHUNK (FD / KCH)               // 4
#define TILE_EL (MD * KCH)              // 8192 halfs per tile
#define TILE_BYTES (TILE_EL * 2)        // 16384
#define BUF_BYTES (3 * TILE_BYTES)      // Ahi, Bhi, Blo
#define SMEM_TOTAL (2 * BUF_BYTES)      // 98304 (double buffered)

// Split-precision K-major scratch: [t*64+b][chunk][m][k_local], fp16
__device__ __half g_hi[2 * BSZ * NCHUNK * TILE_EL];   // 8 MB
__device__ __half g_lo[2 * BSZ * NCHUNK * TILE_EL];   // 8 MB

__device__ __forceinline__ uint32_t smem_u32(const void* p) {
    uint32_t a;
    asm("{ .reg .u64 t; cvta.to.shared.u64 t, %1; cvt.u32.u64 %0, t; }"
        : "=r"(a) : "l"(p));
    return a;
}

#define SWZ(o) ((o) ^ (((o) >> 3) & 0x70))

// ---------------- Kernel 1: fp32 -> fp16 hi/lo split + transpose ----------------
__global__ __launch_bounds__(256)
void split_transpose_kernel(const float* __restrict__ m1,
                            const float* __restrict__ m2)
{
    __shared__ float tile[KCH][MD + 1];
    const int tb = blockIdx.x;              // 0..127 = t*64 + b
    const int t  = tb >> 6;
    const int b  = tb & 63;
    const float* src = (t ? m2 : m1) + (size_t)b * FD * MD;
    const int tid = threadIdx.x;

    for (int kc = 0; kc < NCHUNK; kc++) {
        const float* s = src + (size_t)kc * KCH * MD;
#pragma unroll
        for (int it = 0; it < 8; it++) {
            int i4 = it * 256 + tid;               // 0..2047 float4s
            int f  = i4 >> 5;
            int m4 = (i4 & 31) * 4;
            float4 v = *(const float4*)(s + f * MD + m4);
            tile[f][m4]     = v.x;
            tile[f][m4 + 1] = v.y;
            tile[f][m4 + 2] = v.z;
            tile[f][m4 + 3] = v.w;
        }
        __syncthreads();
        size_t base = ((size_t)tb * NCHUNK + kc) * TILE_EL;
#pragma unroll
        for (int it = 0; it < 4; it++) {
            int idx = it * 256 + tid;              // [128 m][8 kgroups]
            int m  = idx >> 3;
            int kl = (idx & 7) * 8;
            __half hv[8], lv[8];
#pragma unroll
            for (int j = 0; j < 8; j++) {
                float x = tile[kl + j][m];
                __half h = __float2half_rn(x);
                hv[j] = h;
                lv[j] = __float2half_rn(x - __half2float(h));
            }
            *(uint4*)(&g_hi[base + (size_t)m * KCH + kl]) = *(const uint4*)hv;
            *(uint4*)(&g_lo[base + (size_t)m * KCH + kl]) = *(const uint4*)lv;
        }
        __syncthreads();
    }
}

// ---------------- Kernel 2: fp16 HMMA Gram + fused histogram ----------------
#define MMA_F16(d, A, B)                                                       \
    asm volatile("mma.sync.aligned.m16n8k16.row.col.f32.f16.f16.f32 "          \
                 "{%0,%1,%2,%3},{%4,%5,%6,%7},{%8,%9},{%0,%1,%2,%3};"          \
                 : "+f"(d[0]), "+f"(d[1]), "+f"(d[2]), "+f"(d[3])              \
                 : "r"(A[0]), "r"(A[1]), "r"(A[2]), "r"(A[3]),                 \
                   "r"(B[0]), "r"(B[1]))

#define LDSM_X4(r, addr)                                                       \
    asm volatile("ldmatrix.sync.aligned.m8n8.x4.shared.b16 {%0,%1,%2,%3},[%4];"\
                 : "=r"(r[0]), "=r"(r[1]), "=r"(r[2]), "=r"(r[3])              \
                 : "r"(addr))

// stage one chunk (Ahi, Bhi, Blo) into a smem buffer via cp.async
__device__ __forceinline__ void load_chunk(uint32_t buf_base,
                                           const __half* gA_hi,
                                           const __half* gB_hi,
                                           const __half* gB_lo,
                                           int tid)
{
    const __half* gs[3] = { gA_hi, gB_hi, gB_lo };
#pragma unroll
    for (int T = 0; T < 3; T++) {
#pragma unroll
        for (int it = 0; it < 4; it++) {
            int idx = it * 256 + tid;           // 1024 16B-chunks per tile
            int m  = idx >> 3;
            int kg = idx & 7;
            uint32_t soff = (uint32_t)T * TILE_BYTES + SWZ((uint32_t)(m * 128 + kg * 16));
            const void* ga = gs[T] + (size_t)m * KCH + kg * 8;
            asm volatile("cp.async.cg.shared.global [%0], [%1], 16;"
                         :: "r"(buf_base + soff), "l"(ga));
        }
    }
    asm volatile("cp.async.commit_group;" ::: "memory");
}

__global__ __launch_bounds__(256, 2)
void pair_hist_mma_kernel(float* __restrict__ out)
{
    extern __shared__ __align__(16) char smem[];
    const uint32_t sb = smem_u32(smem);

    __shared__ float s_bins[NBINS - 1];
    __shared__ float s_wmn[8], s_wmx[8];
    __shared__ float s_mm[2];

    const int tid  = threadIdx.x;
    const int wid  = tid >> 5;
    const int lane = tid & 31;
    const int wm   = wid & 1;     // 2 row-groups of 64
    const int wn   = wid >> 1;    // 4 col-groups of 32

    if (tid < NBINS - 1) s_bins[tid] = 0.0f;

    // unrank pair
    const int bid = blockIdx.x;
    const int t   = (bid >= NPAIR) ? 1 : 0;
    int p = bid - t * NPAIR;
    int a = 0;
    while (p >= BSZ - a) { p -= BSZ - a; a++; }
    const int b = a + p;

    const size_t tA = (size_t)(t * BSZ + a) * NCHUNK * TILE_EL;
    const size_t tB = (size_t)(t * BSZ + b) * NCHUNK * TILE_EL;

    float acc[4][4][4];
#pragma unroll
    for (int i = 0; i < 4; i++)
#pragma unroll
        for (int j = 0; j < 4; j++)
#pragma unroll
            for (int q = 0; q < 4; q++) acc[i][j][q] = 0.0f;

    // ---- swizzled addressing, correct form ----
    // SWZ(o) = o ^ ((o>>3)&0x70): mask is derived from bits 7-9 (= row & 7)
    // and XORs bits 4-6, where (ks*32 + koff) lives. All 8 ldmatrix rows of
    // this thread share row&7 == lane&7, so one mask M for everything:
    //   addr = bufb + ((X + ks*32) ^ M),  X = tile_off + row*128 + koff.
    // koff (bit 4) + ks*32 (bits 5-6) never carry past bit 6, so the XOR is exact.
    const int a_row  = wm * 64 + (lane & 15);
    const int a_koff = (lane >> 4) * 16;
    const int b_row  = wn * 32 + ((lane >> 4) << 3) + (lane & 7);
    const int b_koff = ((lane >> 3) & 1) * 16;
    const uint32_t M = (uint32_t)(lane & 7) << 4;

    uint32_t X[8];   // A0..A3, BH0, BH1, BL0, BL1
#pragma unroll
    for (int mt = 0; mt < 4; mt++)
        X[mt] = (uint32_t)((a_row + mt * 16) * 128 + a_koff);
#pragma unroll
    for (int np = 0; np < 2; np++) {
        uint32_t r = (uint32_t)((b_row + np * 16) * 128 + b_koff);
        X[4 + np] = TILE_BYTES + r;          // Bhi tile
        X[6 + np] = 2 * TILE_BYTES + r;      // Blo tile
    }

    // prologue: chunks 0 and 1 in flight
    load_chunk(sb,             g_hi + tA,           g_hi + tB,           g_lo + tB,           tid);
    load_chunk(sb + BUF_BYTES, g_hi + tA + TILE_EL, g_hi + tB + TILE_EL, g_lo + tB + TILE_EL, tid);

    for (int c = 0; c < NCHUNK; c++) {
        if (c < NCHUNK - 1)
            asm volatile("cp.async.wait_group 1;" ::: "memory");
        else
            asm volatile("cp.async.wait_group 0;" ::: "memory");
        __syncthreads();

        const uint32_t bufb = sb + (uint32_t)(c & 1) * BUF_BYTES;
#pragma unroll
        for (int ks = 0; ks < 4; ks++) {       // 4 k16-steps within KCH=64
            const uint32_t d = (uint32_t)ks * 32;
            uint32_t ahi[4][4];
#pragma unroll
            for (int mt = 0; mt < 4; mt++)
                LDSM_X4(ahi[mt], bufb + ((X[mt] + d) ^ M));
            uint32_t bhi[4][2], blo[4][2];
#pragma unroll
            for (int np = 0; np < 2; np++) {
                uint32_t rh[4], rl[4];
                LDSM_X4(rh, bufb + ((X[4 + np] + d) ^ M));
                LDSM_X4(rl, bufb + ((X[6 + np] + d) ^ M));
                bhi[np * 2][0] = rh[0]; bhi[np * 2][1] = rh[1];
                bhi[np * 2 + 1][0] = rh[2]; bhi[np * 2 + 1][1] = rh[3];
                blo[np * 2][0] = rl[0]; blo[np * 2][1] = rl[1];
                blo[np * 2 + 1][0] = rl[2]; blo[np * 2 + 1][1] = rl[3];
            }
            // all hi*bhi first, then all hi*blo: 15 independent MMAs between
            // any accumulator reuse -> no RAW exposure on the tensor pipe
#pragma unroll
            for (int mt = 0; mt < 4; mt++)
#pragma unroll
                for (int nt = 0; nt < 4; nt++)
                    MMA_F16(acc[mt][nt], ahi[mt], bhi[nt]);
#pragma unroll
            for (int mt = 0; mt < 4; mt++)
#pragma unroll
                for (int nt = 0; nt < 4; nt++)
                    MMA_F16(acc[mt][nt], ahi[mt], blo[nt]);
        }

        if (c + 2 < NCHUNK) {
            __syncthreads();                    // all warps done reading this buffer
            size_t co = (size_t)(c + 2) * TILE_EL;
            load_chunk(bufb, g_hi + tA + co, g_hi + tB + co, g_lo + tB + co, tid);
        }
    }

    // ---- epilogue: histogram over the 64 per-thread accumulators ----
    float* av = &acc[0][0][0];

    float mn = av[0], mx = av[0];
#pragma unroll
    for (int i = 1; i < 64; i++) {
        mn = fminf(mn, av[i]);
        mx = fmaxf(mx, av[i]);
    }
#pragma unroll
    for (int o = 16; o > 0; o >>= 1) {
        mn = fminf(mn, __shfl_xor_sync(0xffffffffu, mn, o));
        mx = fmaxf(mx, __shfl_xor_sync(0xffffffffu, mx, o));
    }
    if (lane == 0) { s_wmn[wid] = mn; s_wmx[wid] = mx; }
    __syncthreads();
    if (tid == 0) {
        float m0 = s_wmn[0], m1v = s_wmx[0];
#pragma unroll
        for (int w = 1; w < 8; w++) {
            m0  = fminf(m0,  s_wmn[w]);
            m1v = fmaxf(m1v, s_wmx[w]);
        }
        s_mm[0] = m0; s_mm[1] = m1v;
    }
    __syncthreads();
    mn = s_mm[0]; mx = s_mm[1];

    const float denom = (mx > mn) ? (mx - mn) : 1.0f;
    const float scale = 8.0f / denom;
    const float off   = -mn * scale;
    float cge[7] = {0, 0, 0, 0, 0, 0, 0};
#pragma unroll
    for (int i = 0; i < 64; i++) {
        float y = fmaf(av[i], scale, off);
#pragma unroll
        for (int q = 0; q < 7; q++)
            cge[q] += (y >= (float)(q + 1)) ? 1.0f : 0.0f;
    }
#pragma unroll
    for (int q = 0; q < 7; q++) {
#pragma unroll
        for (int o = 16; o > 0; o >>= 1)
            cge[q] += __shfl_xor_sync(0xffffffffu, cge[q], o);
        if (lane == 0) atomicAdd(&s_bins[q], cge[q]);
    }
    __syncthreads();

    if (tid == 0) {
        float C[9];
        C[0] = (float)(MD * MD);
        C[8] = 0.0f;
#pragma unroll
        for (int q = 1; q < 8; q++) C[q] = s_bins[q - 1];
        float h[8], nrm = 0.0f;
#pragma unroll
        for (int q = 0; q < 8; q++) {
            h[q] = C[q] - C[q + 1];
            nrm += h[q] * h[q];
        }
        const float inv = 1.0f / sqrtf(nrm);
        const int r1 = a * BSZ + b;
        const int r2 = b * BSZ + a;
        float* o1 = out + (size_t)r1 * 16 + t * 8;
        float* o2 = out + (size_t)r2 * 16 + t * 8;
#pragma unroll
        for (int q = 0; q < 8; q++) {
            float v = h[q] * inv;
            o1[q] = v;
            o2[q] = v;
        }
    }
}

// ---------------- launch ----------------
extern "C" void kernel_launch(void* const* d_in, const int* in_sizes, int n_in,
                              void* d_out, int out_size)
{
    const float* m1 = (const float*)d_in[0];
    const float* m2 = (const float*)d_in[1];
    float* out = (float*)d_out;

    cudaFuncSetAttribute(pair_hist_mma_kernel,
                         cudaFuncAttributeMaxDynamicSharedMemorySize, SMEM_TOTAL);

    split_transpose_kernel<<<2 * BSZ, 256>>>(m1, m2);
    pair_hist_mma_kernel<<<2 * NPAIR, 256, SMEM_TOTAL>>>(out);
}

// round 9
// speedup vs baseline: 1.4208x; 1.4208x over previous
#include <cuda_runtime.h>
#include <cuda_fp16.h>
#include <cstdint>

#define BSZ   64
#define FD    256
#define MD    128
#define NBINS 8
#define NPAIR (BSZ * (BSZ + 1) / 2)     // 2080
#define KCH   64                        // K elements per SMEM chunk
#define NCHUNK (FD / KCH)               // 4
#define TILE_EL (MD * KCH)              // 8192 halfs per tile
#define TILE_BYTES (TILE_EL * 2)        // 16384
#define BUF_BYTES (2 * TILE_BYTES)      // A, B
#define SMEM_TOTAL (2 * BUF_BYTES)      // 65536 (double buffered)

// fp16 K-major scratch: [t*64+b][chunk][m][k_local]
__device__ __half g_hi[2 * BSZ * NCHUNK * TILE_EL];   // 8 MB

__device__ __forceinline__ uint32_t smem_u32(const void* p) {
    uint32_t a;
    asm("{ .reg .u64 t; cvta.to.shared.u64 t, %1; cvt.u32.u64 %0, t; }"
        : "=r"(a) : "l"(p));
    return a;
}

#define SWZ(o) ((o) ^ (((o) >> 3) & 0x70))

// ---------------- Kernel 1: fp32 -> fp16 + transpose to K-major ----------------
__global__ __launch_bounds__(256)
void split_transpose_kernel(const float* __restrict__ m1,
                            const float* __restrict__ m2)
{
    __shared__ float tile[KCH][MD + 1];
    const int tb = blockIdx.x;              // 0..127 = t*64 + b
    const int t  = tb >> 6;
    const int b  = tb & 63;
    const float* src = (t ? m2 : m1) + (size_t)b * FD * MD;
    const int tid = threadIdx.x;

    for (int kc = 0; kc < NCHUNK; kc++) {
        const float* s = src + (size_t)kc * KCH * MD;
#pragma unroll
        for (int it = 0; it < 8; it++) {
            int i4 = it * 256 + tid;               // 0..2047 float4s
            int f  = i4 >> 5;
            int m4 = (i4 & 31) * 4;
            float4 v = *(const float4*)(s + f * MD + m4);
            tile[f][m4]     = v.x;
            tile[f][m4 + 1] = v.y;
            tile[f][m4 + 2] = v.z;
            tile[f][m4 + 3] = v.w;
        }
        __syncthreads();
        size_t base = ((size_t)tb * NCHUNK + kc) * TILE_EL;
#pragma unroll
        for (int it = 0; it < 4; it++) {
            int idx = it * 256 + tid;              // [128 m][8 kgroups]
            int m  = idx >> 3;
            int kl = (idx & 7) * 8;
            __half hv[8];
#pragma unroll
            for (int j = 0; j < 8; j++)
                hv[j] = __float2half_rn(tile[kl + j][m]);
            *(uint4*)(&g_hi[base + (size_t)m * KCH + kl]) = *(const uint4*)hv;
        }
        __syncthreads();
    }
}

// ---------------- Kernel 2: fp16 HMMA Gram + fused histogram ----------------
#define MMA_F16(d, A, B)                                                       \
    asm volatile("mma.sync.aligned.m16n8k16.row.col.f32.f16.f16.f32 "          \
                 "{%0,%1,%2,%3},{%4,%5,%6,%7},{%8,%9},{%0,%1,%2,%3};"          \
                 : "+f"(d[0]), "+f"(d[1]), "+f"(d[2]), "+f"(d[3])              \
                 : "r"(A[0]), "r"(A[1]), "r"(A[2]), "r"(A[3]),                 \
                   "r"(B[0]), "r"(B[1]))

#define LDSM_X4(r, addr)                                                       \
    asm volatile("ldmatrix.sync.aligned.m8n8.x4.shared.b16 {%0,%1,%2,%3},[%4];"\
                 : "=r"(r[0]), "=r"(r[1]), "=r"(r[2]), "=r"(r[3])              \
                 : "r"(addr))

// stage one chunk (A, B) into a smem buffer via cp.async
__device__ __forceinline__ void load_chunk(uint32_t buf_base,
                                           const __half* gA,
                                           const __half* gB,
                                           int tid)
{
    const __half* gs[2] = { gA, gB };
#pragma unroll
    for (int T = 0; T < 2; T++) {
#pragma unroll
        for (int it = 0; it < 4; it++) {
            int idx = it * 256 + tid;           // 1024 16B-chunks per tile
            int m  = idx >> 3;
            int kg = idx & 7;
            uint32_t soff = (uint32_t)T * TILE_BYTES + SWZ((uint32_t)(m * 128 + kg * 16));
            const void* ga = gs[T] + (size_t)m * KCH + kg * 8;
            asm volatile("cp.async.cg.shared.global [%0], [%1], 16;"
                         :: "r"(buf_base + soff), "l"(ga));
        }
    }
    asm volatile("cp.async.commit_group;" ::: "memory");
}

__global__ __launch_bounds__(256, 2)
void pair_hist_mma_kernel(float* __restrict__ out)
{
    extern __shared__ __align__(16) char smem[];
    const uint32_t sb = smem_u32(smem);

    __shared__ float s_bins[NBINS - 1];
    __shared__ float s_wmn[8], s_wmx[8];
    __shared__ float s_mm[2];

    const int tid  = threadIdx.x;
    const int wid  = tid >> 5;
    const int lane = tid & 31;
    const int wm   = wid & 1;     // 2 row-groups of 64
    const int wn   = wid >> 1;    // 4 col-groups of 32

    if (tid < NBINS - 1) s_bins[tid] = 0.0f;

    // unrank pair
    const int bid = blockIdx.x;
    const int t   = (bid >= NPAIR) ? 1 : 0;
    int p = bid - t * NPAIR;
    int a = 0;
    while (p >= BSZ - a) { p -= BSZ - a; a++; }
    const int b = a + p;

    const size_t tA = (size_t)(t * BSZ + a) * NCHUNK * TILE_EL;
    const size_t tB = (size_t)(t * BSZ + b) * NCHUNK * TILE_EL;

    float acc[4][4][4];
#pragma unroll
    for (int i = 0; i < 4; i++)
#pragma unroll
        for (int j = 0; j < 4; j++)
#pragma unroll
            for (int q = 0; q < 4; q++) acc[i][j][q] = 0.0f;

    // swizzled addressing: mask M = (lane&7)<<4 XORs bits 4-6;
    // (koff + ks*32) <= 112 never carries past bit 6, so XOR after add is exact.
    const int a_row  = wm * 64 + (lane & 15);
    const int a_koff = (lane >> 4) * 16;
    const int b_row  = wn * 32 + ((lane >> 4) << 3) + (lane & 7);
    const int b_koff = ((lane >> 3) & 1) * 16;
    const uint32_t M = (uint32_t)(lane & 7) << 4;

    uint32_t X[6];   // A0..A3, B0, B1
#pragma unroll
    for (int mt = 0; mt < 4; mt++)
        X[mt] = (uint32_t)((a_row + mt * 16) * 128 + a_koff);
#pragma unroll
    for (int np = 0; np < 2; np++)
        X[4 + np] = TILE_BYTES + (uint32_t)((b_row + np * 16) * 128 + b_koff);

    // prologue: chunks 0 and 1 in flight
    load_chunk(sb,             g_hi + tA,           g_hi + tB,           tid);
    load_chunk(sb + BUF_BYTES, g_hi + tA + TILE_EL, g_hi + tB + TILE_EL, tid);

    for (int c = 0; c < NCHUNK; c++) {
        if (c < NCHUNK - 1)
            asm volatile("cp.async.wait_group 1;" ::: "memory");
        else
            asm volatile("cp.async.wait_group 0;" ::: "memory");
        __syncthreads();

        const uint32_t bufb = sb + (uint32_t)(c & 1) * BUF_BYTES;
#pragma unroll
        for (int ks = 0; ks < 4; ks++) {       // 4 k16-steps within KCH=64
            const uint32_t d = (uint32_t)ks * 32;
            uint32_t ahi[4][4];
#pragma unroll
            for (int mt = 0; mt < 4; mt++)
                LDSM_X4(ahi[mt], bufb + ((X[mt] + d) ^ M));
            uint32_t bhi[4][2];
#pragma unroll
            for (int np = 0; np < 2; np++) {
                uint32_t rh[4];
                LDSM_X4(rh, bufb + ((X[4 + np] + d) ^ M));
                bhi[np * 2][0] = rh[0]; bhi[np * 2][1] = rh[1];
                bhi[np * 2 + 1][0] = rh[2]; bhi[np * 2 + 1][1] = rh[3];
            }
            // 16 fully independent MMAs
#pragma unroll
            for (int mt = 0; mt < 4; mt++)
#pragma unroll
                for (int nt = 0; nt < 4; nt++)
                    MMA_F16(acc[mt][nt], ahi[mt], bhi[nt]);
        }

        if (c + 2 < NCHUNK) {
            __syncthreads();                    // all warps done reading this buffer
            size_t co = (size_t)(c + 2) * TILE_EL;
            load_chunk(bufb, g_hi + tA + co, g_hi + tB + co, tid);
        }
    }

    // ---- epilogue: histogram over the 64 per-thread accumulators ----
    float* av = &acc[0][0][0];

    float mn = av[0], mx = av[0];
#pragma unroll
    for (int i = 1; i < 64; i++) {
        mn = fminf(mn, av[i]);
        mx = fmaxf(mx, av[i]);
    }
#pragma unroll
    for (int o = 16; o > 0; o >>= 1) {
        mn = fminf(mn, __shfl_xor_sync(0xffffffffu, mn, o));
        mx = fmaxf(mx, __shfl_xor_sync(0xffffffffu, mx, o));
    }
    if (lane == 0) { s_wmn[wid] = mn; s_wmx[wid] = mx; }
    __syncthreads();
    if (tid == 0) {
        float m0 = s_wmn[0], m1v = s_wmx[0];
#pragma unroll
        for (int w = 1; w < 8; w++) {
            m0  = fminf(m0,  s_wmn[w]);
            m1v = fmaxf(m1v, s_wmx[w]);
        }
        s_mm[0] = m0; s_mm[1] = m1v;
    }
    __syncthreads();
    mn = s_mm[0]; mx = s_mm[1];

    const float denom = (mx > mn) ? (mx - mn) : 1.0f;
    const float scale = 8.0f / denom;
    const float off   = -mn * scale;
    float cge[7] = {0, 0, 0, 0, 0, 0, 0};
#pragma unroll
    for (int i = 0; i < 64; i++) {
        float y = fmaf(av[i], scale, off);
#pragma unroll
        for (int q = 0; q < 7; q++)
            cge[q] += (y >= (float)(q + 1)) ? 1.0f : 0.0f;
    }
#pragma unroll
    for (int q = 0; q < 7; q++) {
#pragma unroll
        for (int o = 16; o > 0; o >>= 1)
            cge[q] += __shfl_xor_sync(0xffffffffu, cge[q], o);
        if (lane == 0) atomicAdd(&s_bins[q], cge[q]);
    }
    __syncthreads();

    if (tid == 0) {
        float C[9];
        C[0] = (float)(MD * MD);
        C[8] = 0.0f;
#pragma unroll
        for (int q = 1; q < 8; q++) C[q] = s_bins[q - 1];
        float h[8], nrm = 0.0f;
#pragma unroll
        for (int q = 0; q < 8; q++) {
            h[q] = C[q] - C[q + 1];
            nrm += h[q] * h[q];
        }
        const float inv = 1.0f / sqrtf(nrm);
        const int r1 = a * BSZ + b;
        const int r2 = b * BSZ + a;
        float* o1 = out + (size_t)r1 * 16 + t * 8;
        float* o2 = out + (size_t)r2 * 16 + t * 8;
#pragma unroll
        for (int q = 0; q < 8; q++) {
            float v = h[q] * inv;
            o1[q] = v;
            o2[q] = v;
        }
    }
}

// ---------------- launch ----------------
extern "C" void kernel_launch(void* const* d_in, const int* in_sizes, int n_in,
                              void* d_out, int out_size)
{
    const float* m1 = (const float*)d_in[0];
    const float* m2 = (const float*)d_in[1];
    float* out = (float*)d_out;

    cudaFuncSetAttribute(pair_hist_mma_kernel,
                         cudaFuncAttributeMaxDynamicSharedMemorySize, SMEM_TOTAL);

    split_transpose_kernel<<<2 * BSZ, 256>>>(m1, m2);
    pair_hist_mma_kernel<<<2 * NPAIR, 256, SMEM_TOTAL>>>(out);
}

// round 11
// speedup vs baseline: 1.6663x; 1.1727x over previous
#include <cuda_runtime.h>
#include <cuda_fp16.h>
#include <cstdint>

#define BSZ   64
#define FD    256
#define MD    128
#define NBINS 8
#define NPAIR (BSZ * (BSZ + 1) / 2)     // 2080
#define KCH   64                        // K elements per SMEM chunk
#define NCHUNK (FD / KCH)               // 4
#define TILE_EL (MD * KCH)              // 8192 halfs per tile
#define TILE_BYTES (TILE_EL * 2)        // 16384
#define BUF_BYTES (2 * TILE_BYTES)      // A, B
#define SMEM_TOTAL (2 * BUF_BYTES)      // 65536 (double buffered)

// fp16 K-major scratch: [t*64+b][chunk][m][k_local]
__device__ __half g_hi[2 * BSZ * NCHUNK * TILE_EL];   // 8 MB

__device__ __forceinline__ uint32_t smem_u32(const void* p) {
    uint32_t a;
    asm("{ .reg .u64 t; cvta.to.shared.u64 t, %1; cvt.u32.u64 %0, t; }"
        : "=r"(a) : "l"(p));
    return a;
}

#define SWZ(o) ((o) ^ (((o) >> 3) & 0x70))

// ---------------- Kernel 1: fp32 -> fp16 + transpose, one chunk per CTA ----------------
__global__ __launch_bounds__(256)
void split_transpose_kernel(const float* __restrict__ m1,
                            const float* __restrict__ m2)
{
    __shared__ float tile[KCH][MD + 1];
    const int cid = blockIdx.x;             // 0..511 = tb*4 + kc
    const int tb = cid >> 2;
    const int kc = cid & 3;
    const int t  = tb >> 6;
    const int b  = tb & 63;
    const float* src = (t ? m2 : m1) + (size_t)b * FD * MD + (size_t)kc * KCH * MD;
    const int tid = threadIdx.x;

#pragma unroll
    for (int it = 0; it < 8; it++) {
        int i4 = it * 256 + tid;               // 0..2047 float4s
        int f  = i4 >> 5;
        int m4 = (i4 & 31) * 4;
        float4 v = *(const float4*)(src + f * MD + m4);
        tile[f][m4]     = v.x;
        tile[f][m4 + 1] = v.y;
        tile[f][m4 + 2] = v.z;
        tile[f][m4 + 3] = v.w;
    }
    __syncthreads();
    size_t base = ((size_t)tb * NCHUNK + kc) * TILE_EL;
#pragma unroll
    for (int it = 0; it < 4; it++) {
        int idx = it * 256 + tid;              // [128 m][8 kgroups]
        int m  = idx >> 3;
        int kl = (idx & 7) * 8;
        __half hv[8];
#pragma unroll
        for (int j = 0; j < 8; j++)
            hv[j] = __float2half_rn(tile[kl + j][m]);
        *(uint4*)(&g_hi[base + (size_t)m * KCH + kl]) = *(const uint4*)hv;
    }
}

// ---------------- Kernel 2: fp16 HMMA Gram + fused histogram ----------------
#define MMA_F16(d, A, B)                                                       \
    asm volatile("mma.sync.aligned.m16n8k16.row.col.f32.f16.f16.f32 "          \
                 "{%0,%1,%2,%3},{%4,%5,%6,%7},{%8,%9},{%0,%1,%2,%3};"          \
                 : "+f"(d[0]), "+f"(d[1]), "+f"(d[2]), "+f"(d[3])              \
                 : "r"(A[0]), "r"(A[1]), "r"(A[2]), "r"(A[3]),                 \
                   "r"(B[0]), "r"(B[1]))

#define LDSM_X4(r, addr)                                                       \
    asm volatile("ldmatrix.sync.aligned.m8n8.x4.shared.b16 {%0,%1,%2,%3},[%4];"\
                 : "=r"(r[0]), "=r"(r[1]), "=r"(r[2]), "=r"(r[3])              \
                 : "r"(addr))

// stage one chunk (A, B) into a smem buffer via cp.async
__device__ __forceinline__ void load_chunk(uint32_t buf_base,
                                           const __half* gA,
                                           const __half* gB,
                                           int tid)
{
    const __half* gs[2] = { gA, gB };
#pragma unroll
    for (int T = 0; T < 2; T++) {
#pragma unroll
        for (int it = 0; it < 4; it++) {
            int idx = it * 256 + tid;           // 1024 16B-chunks per tile
            int m  = idx >> 3;
            int kg = idx & 7;
            uint32_t soff = (uint32_t)T * TILE_BYTES + SWZ((uint32_t)(m * 128 + kg * 16));
            const void* ga = gs[T] + (size_t)m * KCH + kg * 8;
            asm volatile("cp.async.cg.shared.global [%0], [%1], 16;"
                         :: "r"(buf_base + soff), "l"(ga));
        }
    }
    asm volatile("cp.async.commit_group;" ::: "memory");
}

__global__ __launch_bounds__(256, 2)
void pair_hist_mma_kernel(float* __restrict__ out)
{
    extern __shared__ __align__(16) char smem[];
    const uint32_t sb = smem_u32(smem);

    __shared__ int   s_ibins[NBINS];
    __shared__ float s_wmn[8], s_wmx[8];
    __shared__ float s_mm[2];

    const int tid  = threadIdx.x;
    const int wid  = tid >> 5;
    const int lane = tid & 31;
    const int wm   = wid & 1;     // 2 row-groups of 64
    const int wn   = wid >> 1;    // 4 col-groups of 32

    if (tid < NBINS) s_ibins[tid] = 0;

    // unrank pair
    const int bid = blockIdx.x;
    const int t   = (bid >= NPAIR) ? 1 : 0;
    int p = bid - t * NPAIR;
    int a = 0;
    while (p >= BSZ - a) { p -= BSZ - a; a++; }
    const int b = a + p;

    const size_t tA = (size_t)(t * BSZ + a) * NCHUNK * TILE_EL;
    const size_t tB = (size_t)(t * BSZ + b) * NCHUNK * TILE_EL;

    float acc[4][4][4];
#pragma unroll
    for (int i = 0; i < 4; i++)
#pragma unroll
        for (int j = 0; j < 4; j++)
#pragma unroll
            for (int q = 0; q < 4; q++) acc[i][j][q] = 0.0f;

    // swizzled addressing: mask M = (lane&7)<<4 XORs bits 4-6;
    // (koff + ks*32) <= 112 never carries past bit 6, so XOR after add is exact.
    const int a_row  = wm * 64 + (lane & 15);
    const int a_koff = (lane >> 4) * 16;
    const int b_row  = wn * 32 + ((lane >> 4) << 3) + (lane & 7);
    const int b_koff = ((lane >> 3) & 1) * 16;
    const uint32_t M = (uint32_t)(lane & 7) << 4;

    uint32_t X[6];   // A0..A3, B0, B1
#pragma unroll
    for (int mt = 0; mt < 4; mt++)
        X[mt] = (uint32_t)((a_row + mt * 16) * 128 + a_koff);
#pragma unroll
    for (int np = 0; np < 2; np++)
        X[4 + np] = TILE_BYTES + (uint32_t)((b_row + np * 16) * 128 + b_koff);

    // prologue: chunks 0 and 1 in flight
    load_chunk(sb,             g_hi + tA,           g_hi + tB,           tid);
    load_chunk(sb + BUF_BYTES, g_hi + tA + TILE_EL, g_hi + tB + TILE_EL, tid);

    for (int c = 0; c < NCHUNK; c++) {
        if (c < NCHUNK - 1)
            asm volatile("cp.async.wait_group 1;" ::: "memory");
        else
            asm volatile("cp.async.wait_group 0;" ::: "memory");
        __syncthreads();

        const uint32_t bufb = sb + (uint32_t)(c & 1) * BUF_BYTES;
#pragma unroll
        for (int ks = 0; ks < 4; ks++) {       // 4 k16-steps within KCH=64
            const uint32_t d = (uint32_t)ks * 32;
            uint32_t ahi[4][4];
#pragma unroll
            for (int mt = 0; mt < 4; mt++)
                LDSM_X4(ahi[mt], bufb + ((X[mt] + d) ^ M));
            uint32_t bhi[4][2];
#pragma unroll
            for (int np = 0; np < 2; np++) {
                uint32_t rh[4];
                LDSM_X4(rh, bufb + ((X[4 + np] + d) ^ M));
                bhi[np * 2][0] = rh[0]; bhi[np * 2][1] = rh[1];
                bhi[np * 2 + 1][0] = rh[2]; bhi[np * 2 + 1][1] = rh[3];
            }
            // 16 fully independent MMAs
#pragma unroll
            for (int mt = 0; mt < 4; mt++)
#pragma unroll
                for (int nt = 0; nt < 4; nt++)
                    MMA_F16(acc[mt][nt], ahi[mt], bhi[nt]);
        }

        if (c + 2 < NCHUNK) {
            __syncthreads();                    // all warps done reading this buffer
            size_t co = (size_t)(c + 2) * TILE_EL;
            load_chunk(bufb, g_hi + tA + co, g_hi + tB + co, tid);
        }
    }

    // ---- epilogue: min/max then integer-packed histogram ----
    float* av = &acc[0][0][0];

    float mn = av[0], mx = av[0];
#pragma unroll
    for (int i = 1; i < 64; i++) {
        mn = fminf(mn, av[i]);
        mx = fmaxf(mx, av[i]);
    }
#pragma unroll
    for (int o = 16; o > 0; o >>= 1) {
        mn = fminf(mn, __shfl_xor_sync(0xffffffffu, mn, o));
        mx = fmaxf(mx, __shfl_xor_sync(0xffffffffu, mx, o));
    }
    if (lane == 0) { s_wmn[wid] = mn; s_wmx[wid] = mx; }
    __syncthreads();
    if (tid == 0) {
        float m0 = s_wmn[0], m1v = s_wmx[0];
#pragma unroll
        for (int w = 1; w < 8; w++) {
            m0  = fminf(m0,  s_wmn[w]);
            m1v = fmaxf(m1v, s_wmx[w]);
        }
        s_mm[0] = m0; s_mm[1] = m1v;
    }
    __syncthreads();
    mn = s_mm[0]; mx = s_mm[1];

    // idx = min(trunc(y), 7) == #thresholds passed (bit-identical to the
    // cumulative scheme: y in [q,q+1) -> bin q; y=8 clamps to 7; tiny
    // negative y truncates to 0). Byte-packed counters: 4 bins per uint32,
    // per-thread max 64 per byte.
    const float denom = (mx > mn) ? (mx - mn) : 1.0f;
    const float scale = 8.0f / denom;
    const float off   = -mn * scale;
    uint32_t c0 = 0, c1 = 0;
#pragma unroll
    for (int i = 0; i < 64; i++) {
        float y = fmaf(av[i], scale, off);
        int idx = (int)y;
        idx = min(idx, 7);
        uint32_t inc = 1u << ((idx & 3) << 3);
        if (idx < 4) c0 += inc; else c1 += inc;
    }
    // expand bytes -> 16-bit fields (warp max 32*64 = 2048, no overflow)
    uint32_t e[4];
    e[0] = __byte_perm(c0, 0, 0x4140);
    e[1] = __byte_perm(c0, 0, 0x4342);
    e[2] = __byte_perm(c1, 0, 0x4140);
    e[3] = __byte_perm(c1, 0, 0x4342);
#pragma unroll
    for (int o = 16; o > 0; o >>= 1) {
#pragma unroll
        for (int k = 0; k < 4; k++)
            e[k] += __shfl_xor_sync(0xffffffffu, e[k], o);
    }
    if (lane == 0) {
#pragma unroll
        for (int k = 0; k < 4; k++) {
            atomicAdd(&s_ibins[2 * k],     (int)(e[k] & 0xffffu));
            atomicAdd(&s_ibins[2 * k + 1], (int)(e[k] >> 16));
        }
    }
    __syncthreads();

    if (tid == 0) {
        float h[8], nrm = 0.0f;
#pragma unroll
        for (int q = 0; q < 8; q++) {
            h[q] = (float)s_ibins[q];
            nrm += h[q] * h[q];
        }
        const float inv = 1.0f / sqrtf(nrm);
        const int r1 = a * BSZ + b;
        const int r2 = b * BSZ + a;
        float* o1 = out + (size_t)r1 * 16 + t * 8;
        float* o2 = out + (size_t)r2 * 16 + t * 8;
#pragma unroll
        for (int q = 0; q < 8; q++) {
            float v = h[q] * inv;
            o1[q] = v;
            o2[q] = v;
        }
    }
}

// ---------------- launch ----------------
extern "C" void kernel_launch(void* const* d_in, const int* in_sizes, int n_in,
                              void* d_out, int out_size)
{
    const float* m1 = (const float*)d_in[0];
    const float* m2 = (const float*)d_in[1];
    float* out = (float*)d_out;

    cudaFuncSetAttribute(pair_hist_mma_kernel,
                         cudaFuncAttributeMaxDynamicSharedMemorySize, SMEM_TOTAL);

    split_transpose_kernel<<<2 * BSZ * NCHUNK, 256>>>(m1, m2);
    pair_hist_mma_kernel<<<2 * NPAIR, 256, SMEM_TOTAL>>>(out);
}